// round 8
// baseline (speedup 1.0000x reference)
#include <cuda_runtime.h>
#include <cuda_bf16.h>

// Problem constants (fixed shapes from reference setup_inputs)
#define N_NODES   30000
#define N_EDGES   480000
#define N_GRAPHS  128
#define D_IN      128
#define D_H       256
#define N_CLASSES 60

// ---------------- scratch (static device globals; no allocation) ------------
// g_h : raw GEMM output (gather source for the edge scatter)
// g_a / g_b : ping-pong aggregation accumulators (GEMM epilogue seeds the
//             self-loop term into the buffer that is NOT its input -> no race)
__device__ __align__(16) float g_h[(size_t)N_NODES * D_H];
__device__ __align__(16) float g_a[(size_t)N_NODES * D_H];
__device__ __align__(16) float g_b[(size_t)N_NODES * D_H];
__device__ float g_dinv[N_NODES];              // deg, then rsqrt(deg)
__device__ float g_pool[N_GRAPHS * D_H];
__device__ float g_cnt[N_GRAPHS];

// device-side buffer selector (no host-side symbol address needed)
__device__ __forceinline__ float* buf(int s) {
    return (s == 0) ? g_h : (s == 1) ? g_a : g_b;
}

// ---------------- degree / normalization ------------------------------------
__global__ void k_deg_init() {
    int i = blockIdx.x * blockDim.x + threadIdx.x;
    if (i < N_NODES) g_dinv[i] = 1.0f;  // self-loop contributes 1 to deg
}

// edge_index is int32 on device (harness materializes JAX default int32)
__global__ void k_deg_edges(const int* __restrict__ ei) {
    int e = blockIdx.x * blockDim.x + threadIdx.x;
    if (e < N_EDGES) {
        int d = ei[N_EDGES + e];   // dst row of edge_index
        atomicAdd(&g_dinv[d], 1.0f);
    }
}

__global__ void k_dinv() {
    int i = blockIdx.x * blockDim.x + threadIdx.x;
    if (i < N_NODES) g_dinv[i] = rsqrtf(g_dinv[i]);  // deg >= 1 always
}

// ---------------- GEMM: Y[N,256] = act(A[N,K]) @ W[256,K]^T -----------------
// Epilogue dual-write: g_h = y (gather source), agg = y * dinv[row]^2
// (self-loop term of the aggregation, pre-seeded so the scatter just adds).
// act: if bias != nullptr, input element a at feature k -> relu(a + bias[k]).
#define TM 64
#define TN 64
#define TK 16

__global__ __launch_bounds__(256)
void k_gemm(const float* __restrict__ Aext,   // layer-1 input x, or nullptr
            int a_sel,                        // ... -> buf(a_sel)
            const float* __restrict__ W,
            const float* __restrict__ bias, int N, int K,
            int agg_sel) {
    const float* A = Aext ? Aext : buf(a_sel);
    float* raw = g_h;
    float* agg = buf(agg_sel);

    __shared__ float As[TK][TM];
    __shared__ float Ws[TK][TN];

    const int tid = threadIdx.x;
    const int tx = tid & 15;         // 0..15 -> 4 output cols each
    const int ty = tid >> 4;         // 0..15 -> 4 output rows each
    const int m0 = blockIdx.x * TM;
    const int n0 = blockIdx.y * TN;

    const int lr = tid >> 2;          // row within tile 0..63
    const int lk = (tid & 3) * 4;     // k offset within tile {0,4,8,12}

    float acc[4][4];
#pragma unroll
    for (int i = 0; i < 4; i++)
#pragma unroll
        for (int j = 0; j < 4; j++) acc[i][j] = 0.0f;

    const int arow = m0 + lr;
    const bool arow_ok = (arow < N);

    for (int k0 = 0; k0 < K; k0 += TK) {
        float4 av = make_float4(0.f, 0.f, 0.f, 0.f);
        if (arow_ok) {
            av = *reinterpret_cast<const float4*>(&A[(size_t)arow * K + k0 + lk]);
            if (bias) {
                av.x = fmaxf(av.x + bias[k0 + lk + 0], 0.f);
                av.y = fmaxf(av.y + bias[k0 + lk + 1], 0.f);
                av.z = fmaxf(av.z + bias[k0 + lk + 2], 0.f);
                av.w = fmaxf(av.w + bias[k0 + lk + 3], 0.f);
            }
        }
        As[lk + 0][lr] = av.x; As[lk + 1][lr] = av.y;
        As[lk + 2][lr] = av.z; As[lk + 3][lr] = av.w;

        float4 wv = *reinterpret_cast<const float4*>(&W[(size_t)(n0 + lr) * K + k0 + lk]);
        Ws[lk + 0][lr] = wv.x; Ws[lk + 1][lr] = wv.y;
        Ws[lk + 2][lr] = wv.z; Ws[lk + 3][lr] = wv.w;

        __syncthreads();
#pragma unroll
        for (int kk = 0; kk < TK; kk++) {
            float4 a = *reinterpret_cast<const float4*>(&As[kk][ty * 4]);
            float4 w = *reinterpret_cast<const float4*>(&Ws[kk][tx * 4]);
            acc[0][0] += a.x * w.x; acc[0][1] += a.x * w.y; acc[0][2] += a.x * w.z; acc[0][3] += a.x * w.w;
            acc[1][0] += a.y * w.x; acc[1][1] += a.y * w.y; acc[1][2] += a.y * w.z; acc[1][3] += a.y * w.w;
            acc[2][0] += a.z * w.x; acc[2][1] += a.z * w.y; acc[2][2] += a.z * w.z; acc[2][3] += a.z * w.w;
            acc[3][0] += a.w * w.x; acc[3][1] += a.w * w.y; acc[3][2] += a.w * w.z; acc[3][3] += a.w * w.w;
        }
        __syncthreads();
    }

#pragma unroll
    for (int i = 0; i < 4; i++) {
        int row = m0 + ty * 4 + i;
        if (row >= N) continue;
        float dv = g_dinv[row];
        float d2 = dv * dv;
        size_t off = (size_t)row * D_H + n0 + tx * 4;
        float4 r = make_float4(acc[i][0], acc[i][1], acc[i][2], acc[i][3]);
        *reinterpret_cast<float4*>(&raw[off]) = r;
        float4 g = make_float4(r.x * d2, r.y * d2, r.z * d2, r.w * d2);
        *reinterpret_cast<float4*>(&agg[off]) = g;
    }
}

// ---------------- edge aggregation: out[dst] += g_h[src] * dinv[s]*dinv[d] --
__global__ __launch_bounds__(256)
void k_agg_edges(int out_sel, const int* __restrict__ ei) {
    float* out = buf(out_sel);
    int warp = (blockIdx.x * blockDim.x + threadIdx.x) >> 5;
    int lane = threadIdx.x & 31;
    if (warp >= N_EDGES) return;
    int s = ei[warp];
    int d = ei[N_EDGES + warp];
    float nrm = g_dinv[s] * g_dinv[d];
    const float* hs = g_h + (size_t)s * D_H;
    float* od = out + (size_t)d * D_H;
#pragma unroll
    for (int c = lane; c < D_H; c += 32) {
        atomicAdd(&od[c], __ldg(&hs[c]) * nrm);
    }
}

// ---------------- pooling ----------------------------------------------------
__global__ void k_pool_zero() {
    int i = blockIdx.x * blockDim.x + threadIdx.x;
    if (i < N_GRAPHS * D_H) g_pool[i] = 0.0f;
    if (i < N_GRAPHS) g_cnt[i] = 0.0f;
}

__global__ void k_pool_cnt(const int* __restrict__ batch) {
    int n = blockIdx.x * blockDim.x + threadIdx.x;
    if (n < N_NODES) atomicAdd(&g_cnt[batch[n]], 1.0f);
}

__global__ __launch_bounds__(256)
void k_pool_sum(int h_sel, const float* __restrict__ b3,
                const int* __restrict__ batch) {
    const float* hagg = buf(h_sel);
    int idx = blockIdx.x * blockDim.x + threadIdx.x;
    if (idx >= N_NODES * D_H) return;
    int n = idx >> 8;
    int c = idx & 255;
    float v = fmaxf(hagg[idx] + b3[c], 0.0f);
    atomicAdd(&g_pool[batch[n] * D_H + c], v);
}

// ---------------- final FC ---------------------------------------------------
__global__ void k_fc(const float* __restrict__ Wfc, const float* __restrict__ bfc,
                     float* __restrict__ out) {
    int g = blockIdx.x;
    int c = threadIdx.x;
    if (c >= N_CLASSES) return;
    float inv = 1.0f / fmaxf(g_cnt[g], 1.0f);
    const float* p = &g_pool[g * D_H];
    const float* w = &Wfc[c * D_H];
    float s = 0.0f;
#pragma unroll 8
    for (int k = 0; k < D_H; k++) s += p[k] * w[k];
    out[g * N_CLASSES + c] = s * inv + bfc[c];
}

// ---------------- launch -----------------------------------------------------
extern "C" void kernel_launch(void* const* d_in, const int* in_sizes, int n_in,
                              void* d_out, int out_size) {
    const float* x    = (const float*)d_in[0];
    const int*   ei   = (const int*)d_in[1];    // int32 (harness dtype)
    const int*   batch= (const int*)d_in[2];    // int32
    const float* W1 = (const float*)d_in[3];
    const float* b1 = (const float*)d_in[4];
    const float* W2 = (const float*)d_in[5];
    const float* b2 = (const float*)d_in[6];
    const float* W3 = (const float*)d_in[7];
    const float* b3 = (const float*)d_in[8];
    const float* Wfc= (const float*)d_in[9];
    const float* bfc= (const float*)d_in[10];
    float* out = (float*)d_out;

    const int A = 1, B = 2;   // buffer selectors (0 = g_h)

    // 1) degree -> dinv
    k_deg_init<<<(N_NODES + 255) / 256, 256>>>();
    k_deg_edges<<<(N_EDGES + 255) / 256, 256>>>(ei);
    k_dinv<<<(N_NODES + 255) / 256, 256>>>();

    dim3 ggrid((N_NODES + TM - 1) / TM, D_H / TN);
    int agg_blocks = (N_EDGES * 32 + 255) / 256;

    // 2) layer 1: g_h = x @ W1^T ; g_a = g_h*dinv^2 ; g_a += scatter(g_h)
    k_gemm<<<ggrid, 256>>>(x, 0, W1, nullptr, N_NODES, D_IN, A);
    k_agg_edges<<<agg_blocks, 256>>>(A, ei);

    // 3) layer 2: input relu(g_a + b1) -> agg into g_b
    k_gemm<<<ggrid, 256>>>(nullptr, A, W2, b1, N_NODES, D_H, B);
    k_agg_edges<<<agg_blocks, 256>>>(B, ei);

    // 4) layer 3: input relu(g_b + b2) -> agg into g_a
    k_gemm<<<ggrid, 256>>>(nullptr, B, W3, b2, N_NODES, D_H, A);
    k_agg_edges<<<agg_blocks, 256>>>(A, ei);

    // 5) pooling (applies relu(. + b3)) and FC
    k_pool_zero<<<(N_GRAPHS * D_H + 255) / 256, 256>>>();
    k_pool_cnt<<<(N_NODES + 255) / 256, 256>>>(batch);
    k_pool_sum<<<(N_NODES * D_H + 255) / 256, 256>>>(A, b3, batch);
    k_fc<<<N_GRAPHS, 64>>>(Wfc, bfc, out);
}

// round 11
// speedup vs baseline: 1.1856x; 1.1856x over previous
#include <cuda_runtime.h>
#include <cuda_bf16.h>

#define N_NODES   30000
#define N_EDGES   480000
#define N_GRAPHS  128
#define D_IN      128
#define D_H       256
#define N_CLASSES 60

// ---------------- scratch (static device globals; no allocation) ------------
__device__ __align__(16) float g_h[(size_t)N_NODES * D_H];  // h' = y*dinv[row]
__device__ __align__(16) float g_a[(size_t)N_NODES * D_H];  // agg out (L1, L3)
__device__ __align__(16) float g_b[(size_t)N_NODES * D_H];  // agg out (L2)
__device__ float g_dinv[N_NODES];
__device__ int   g_degi[N_NODES];
__device__ int   g_cursor[N_NODES];
__device__ int   g_rowptr[N_NODES + 1];
__device__ int   g_srcidx[N_EDGES];
__device__ int   g_gofs[N_GRAPHS + 1];
__device__ float g_pool[N_GRAPHS * D_H];

__device__ __forceinline__ float* buf(int s) {
    return (s == 0) ? g_h : (s == 1) ? g_a : g_b;
}

// ---------------- CSR build --------------------------------------------------
__global__ void k_zero_int() {
    int i = blockIdx.x * blockDim.x + threadIdx.x;
    if (i < N_NODES) { g_degi[i] = 0; g_cursor[i] = 0; }
}

__global__ void k_deg(const int* __restrict__ ei) {
    int e = blockIdx.x * blockDim.x + threadIdx.x;
    if (e < N_EDGES) atomicAdd(&g_degi[ei[N_EDGES + e]], 1);
}

// single block, 1024 threads: exclusive scan of g_degi -> g_rowptr; also dinv
__global__ __launch_bounds__(1024)
void k_scan() {
    __shared__ int warp_tot[32];
    int tid = threadIdx.x, lane = tid & 31, wid = tid >> 5;
    int carry = 0;
    for (int base = 0; base < N_NODES; base += 1024) {
        int i = base + tid;
        int v = (i < N_NODES) ? g_degi[i] : 0;
        if (i < N_NODES) g_dinv[i] = rsqrtf((float)(v + 1));  // +1 self loop
        int x = v;
#pragma unroll
        for (int o = 1; o < 32; o <<= 1) {
            int y = __shfl_up_sync(0xFFFFFFFFu, x, o);
            if (lane >= o) x += y;
        }
        if (lane == 31) warp_tot[wid] = x;
        __syncthreads();
        if (wid == 0) {
            int t = warp_tot[lane];
#pragma unroll
            for (int o = 1; o < 32; o <<= 1) {
                int y = __shfl_up_sync(0xFFFFFFFFu, t, o);
                if (lane >= o) t += y;
            }
            warp_tot[lane] = t;
        }
        __syncthreads();
        int wpre = (wid == 0) ? 0 : warp_tot[wid - 1];
        if (i < N_NODES) g_rowptr[i] = carry + wpre + x - v;  // exclusive
        carry += warp_tot[31];
        __syncthreads();
    }
    if (tid == 0) g_rowptr[N_NODES] = carry;
}

__global__ void k_fill(const int* __restrict__ ei) {
    int e = blockIdx.x * blockDim.x + threadIdx.x;
    if (e < N_EDGES) {
        int s = ei[e];
        int d = ei[N_EDGES + e];
        int pos = atomicAdd(&g_cursor[d], 1);
        g_srcidx[g_rowptr[d] + pos] = s;
    }
}

// ---------------- GEMM: g_h[N,256] = (act(A) @ W^T) * dinv[row] -------------
#define TM 128
#define TN 128
#define TK 16

__global__ __launch_bounds__(256)
void k_gemm(const float* __restrict__ Aext, int a_sel,
            const float* __restrict__ W,
            const float* __restrict__ bias, int N, int K) {
    const float* A = Aext ? Aext : buf(a_sel);

    __shared__ float As[TK][TM];
    __shared__ float Ws[TK][TN];

    const int tid = threadIdx.x;
    const int tx = tid & 15;          // n micro-tile 0..15
    const int ty = tid >> 4;          // m micro-tile 0..15
    const int m0 = blockIdx.x * TM;
    const int n0 = blockIdx.y * TN;

    float acc[8][8];
#pragma unroll
    for (int i = 0; i < 8; i++)
#pragma unroll
        for (int j = 0; j < 8; j++) acc[i][j] = 0.0f;

    for (int k0 = 0; k0 < K; k0 += TK) {
#pragma unroll
        for (int l = 0; l < 2; l++) {
            int f = tid + l * 256;       // float4 id 0..511
            int row = f >> 2;            // 0..127
            int kk = (f & 3) * 4;
            // A tile
            int arow = m0 + row;
            float4 av = make_float4(0.f, 0.f, 0.f, 0.f);
            if (arow < N) {
                av = *reinterpret_cast<const float4*>(&A[(size_t)arow * K + k0 + kk]);
                if (bias) {
                    av.x = fmaxf(av.x + bias[k0 + kk + 0], 0.f);
                    av.y = fmaxf(av.y + bias[k0 + kk + 1], 0.f);
                    av.z = fmaxf(av.z + bias[k0 + kk + 2], 0.f);
                    av.w = fmaxf(av.w + bias[k0 + kk + 3], 0.f);
                }
            }
            As[kk + 0][row] = av.x; As[kk + 1][row] = av.y;
            As[kk + 2][row] = av.z; As[kk + 3][row] = av.w;
            // W tile (rows n0+row < 256 always: grid.y * TN == D_H)
            float4 wv = *reinterpret_cast<const float4*>(&W[(size_t)(n0 + row) * K + k0 + kk]);
            Ws[kk + 0][row] = wv.x; Ws[kk + 1][row] = wv.y;
            Ws[kk + 2][row] = wv.z; Ws[kk + 3][row] = wv.w;
        }
        __syncthreads();
#pragma unroll
        for (int kk = 0; kk < TK; kk++) {
            float a[8], w[8];
            *reinterpret_cast<float4*>(a)     = *reinterpret_cast<const float4*>(&As[kk][ty * 8]);
            *reinterpret_cast<float4*>(a + 4) = *reinterpret_cast<const float4*>(&As[kk][ty * 8 + 4]);
            *reinterpret_cast<float4*>(w)     = *reinterpret_cast<const float4*>(&Ws[kk][tx * 8]);
            *reinterpret_cast<float4*>(w + 4) = *reinterpret_cast<const float4*>(&Ws[kk][tx * 8 + 4]);
#pragma unroll
            for (int i = 0; i < 8; i++)
#pragma unroll
                for (int j = 0; j < 8; j++) acc[i][j] += a[i] * w[j];
        }
        __syncthreads();
    }

#pragma unroll
    for (int i = 0; i < 8; i++) {
        int row = m0 + ty * 8 + i;
        if (row >= N) continue;
        float dv = g_dinv[row];
        size_t off = (size_t)row * D_H + n0 + tx * 8;
        float4 r0 = make_float4(acc[i][0] * dv, acc[i][1] * dv, acc[i][2] * dv, acc[i][3] * dv);
        float4 r1 = make_float4(acc[i][4] * dv, acc[i][5] * dv, acc[i][6] * dv, acc[i][7] * dv);
        *reinterpret_cast<float4*>(&g_h[off])     = r0;
        *reinterpret_cast<float4*>(&g_h[off + 4]) = r1;
    }
}

// ------- pull aggregation: out[d] = dinv[d]*(h'[d] + sum h'[src]) -----------
__global__ __launch_bounds__(256)
void k_agg_csr(int out_sel) {
    float* out = buf(out_sel);
    const int d = blockIdx.x;
    const int c = threadIdx.x;
    const int beg = g_rowptr[d];
    const int end = g_rowptr[d + 1];

    __shared__ int s_idx[128];

    float acc = g_h[(size_t)d * D_H + c];   // self-loop term
    for (int b = beg; b < end; b += 128) {
        int m = min(128, end - b);
        if (c < m) s_idx[c] = g_srcidx[b + c];
        __syncthreads();
        int i = 0;
        for (; i + 4 <= m; i += 4) {
            const float* p0 = g_h + (size_t)s_idx[i + 0] * D_H;
            const float* p1 = g_h + (size_t)s_idx[i + 1] * D_H;
            const float* p2 = g_h + (size_t)s_idx[i + 2] * D_H;
            const float* p3 = g_h + (size_t)s_idx[i + 3] * D_H;
            acc += p0[c] + p1[c] + p2[c] + p3[c];
        }
        for (; i < m; i++) acc += g_h[(size_t)s_idx[i] * D_H + c];
        __syncthreads();
    }
    out[(size_t)d * D_H + c] = acc * g_dinv[d];
}

// ---------------- pooling (batch is sorted -> contiguous segments) ----------
__global__ void k_gofs(const int* __restrict__ batch) {
    int n = blockIdx.x * blockDim.x + threadIdx.x;
    if (n >= N_NODES) return;
    int b = batch[n];
    int bp = (n == 0) ? -1 : batch[n - 1];
    for (int g = bp + 1; g <= b; g++) g_gofs[g] = n;
    if (n == N_NODES - 1)
        for (int g = b + 1; g <= N_GRAPHS; g++) g_gofs[g] = N_NODES;
}

__global__ __launch_bounds__(256)
void k_pool(const float* __restrict__ b3) {
    int g = blockIdx.x, c = threadIdx.x;
    int beg = g_gofs[g], end = g_gofs[g + 1];
    float bc = b3[c];
    float acc = 0.0f;
    int n = beg;
    for (; n + 4 <= end; n += 4) {
        float v0 = fmaxf(g_a[(size_t)(n + 0) * D_H + c] + bc, 0.f);
        float v1 = fmaxf(g_a[(size_t)(n + 1) * D_H + c] + bc, 0.f);
        float v2 = fmaxf(g_a[(size_t)(n + 2) * D_H + c] + bc, 0.f);
        float v3 = fmaxf(g_a[(size_t)(n + 3) * D_H + c] + bc, 0.f);
        acc += v0 + v1 + v2 + v3;
    }
    for (; n < end; n++) acc += fmaxf(g_a[(size_t)n * D_H + c] + bc, 0.f);
    float cnt = (float)(end - beg);
    g_pool[g * D_H + c] = acc / fmaxf(cnt, 1.0f);
}

// ---------------- final FC ---------------------------------------------------
__global__ void k_fc(const float* __restrict__ Wfc, const float* __restrict__ bfc,
                     float* __restrict__ out) {
    int g = blockIdx.x;
    int c = threadIdx.x;
    if (c >= N_CLASSES) return;
    const float* p = &g_pool[g * D_H];
    const float* w = &Wfc[c * D_H];
    float s = 0.0f;
#pragma unroll 8
    for (int k = 0; k < D_H; k++) s += p[k] * w[k];
    out[g * N_CLASSES + c] = s + bfc[c];
}

// ---------------- launch -----------------------------------------------------
extern "C" void kernel_launch(void* const* d_in, const int* in_sizes, int n_in,
                              void* d_out, int out_size) {
    const float* x    = (const float*)d_in[0];
    const int*   ei   = (const int*)d_in[1];
    const int*   batch= (const int*)d_in[2];
    const float* W1 = (const float*)d_in[3];
    const float* b1 = (const float*)d_in[4];
    const float* W2 = (const float*)d_in[5];
    const float* b2 = (const float*)d_in[6];
    const float* W3 = (const float*)d_in[7];
    const float* b3 = (const float*)d_in[8];
    const float* Wfc= (const float*)d_in[9];
    const float* bfc= (const float*)d_in[10];
    float* out = (float*)d_out;

    const int A = 1, B = 2;

    // CSR build + dinv
    k_zero_int<<<(N_NODES + 255) / 256, 256>>>();
    k_deg<<<(N_EDGES + 255) / 256, 256>>>(ei);
    k_scan<<<1, 1024>>>();
    k_fill<<<(N_EDGES + 255) / 256, 256>>>(ei);
    k_gofs<<<(N_NODES + 255) / 256, 256>>>(batch);

    dim3 ggrid((N_NODES + TM - 1) / TM, D_H / TN);

    // layer 1
    k_gemm<<<ggrid, 256>>>(x, 0, W1, nullptr, N_NODES, D_IN);
    k_agg_csr<<<N_NODES, 256>>>(A);
    // layer 2
    k_gemm<<<ggrid, 256>>>(nullptr, A, W2, b1, N_NODES, D_H);
    k_agg_csr<<<N_NODES, 256>>>(B);
    // layer 3
    k_gemm<<<ggrid, 256>>>(nullptr, B, W3, b2, N_NODES, D_H);
    k_agg_csr<<<N_NODES, 256>>>(A);

    // pool + fc
    k_pool<<<N_GRAPHS, 256>>>(b3);
    k_fc<<<N_GRAPHS, 64>>>(Wfc, bfc, out);
}

// round 12
// speedup vs baseline: 1.6513x; 1.3929x over previous
#include <cuda_runtime.h>
#include <cuda_bf16.h>
#include <cstdint>

#define N_NODES   30000
#define N_EDGES   480000
#define N_GRAPHS  128
#define D_IN      128
#define D_H       256
#define N_CLASSES 60

// ---------------- scratch (static device globals; no allocation) ------------
__device__ __align__(16) float g_h[(size_t)N_NODES * D_H];  // h' = y*dinv[row]
__device__ __align__(16) float g_a[(size_t)N_NODES * D_H];  // agg out (L1, L3)
__device__ __align__(16) float g_b[(size_t)N_NODES * D_H];  // agg out (L2)
__device__ float g_dinv[N_NODES];
__device__ int   g_degi[N_NODES];
__device__ int   g_cursor[N_NODES];
__device__ int   g_rowptr[N_NODES + 1];
__device__ int   g_srcidx[N_EDGES];
__device__ int   g_gofs[N_GRAPHS + 1];
__device__ float g_pool[N_GRAPHS * D_H];

__device__ __forceinline__ float* buf(int s) {
    return (s == 0) ? g_h : (s == 1) ? g_a : g_b;
}

// round-to-nearest tf32 (unbiased; raw truncation would bias products low)
__device__ __forceinline__ float f2tf(float f) {
    uint32_t u;
    asm("cvt.rna.tf32.f32 %0, %1;" : "=r"(u) : "f"(f));
    return __uint_as_float(u);
}

// ---------------- CSR build --------------------------------------------------
__global__ void k_zero_int() {
    int i = blockIdx.x * blockDim.x + threadIdx.x;
    if (i < N_NODES) { g_degi[i] = 0; g_cursor[i] = 0; }
}

__global__ void k_deg(const int* __restrict__ ei) {
    int e = blockIdx.x * blockDim.x + threadIdx.x;
    if (e < N_EDGES) atomicAdd(&g_degi[ei[N_EDGES + e]], 1);
}

// single block, 1024 threads: exclusive scan of g_degi -> g_rowptr; also dinv
__global__ __launch_bounds__(1024)
void k_scan() {
    __shared__ int warp_tot[32];
    int tid = threadIdx.x, lane = tid & 31, wid = tid >> 5;
    int carry = 0;
    for (int base = 0; base < N_NODES; base += 1024) {
        int i = base + tid;
        int v = (i < N_NODES) ? g_degi[i] : 0;
        if (i < N_NODES) g_dinv[i] = rsqrtf((float)(v + 1));  // +1 self loop
        int x = v;
#pragma unroll
        for (int o = 1; o < 32; o <<= 1) {
            int y = __shfl_up_sync(0xFFFFFFFFu, x, o);
            if (lane >= o) x += y;
        }
        if (lane == 31) warp_tot[wid] = x;
        __syncthreads();
        if (wid == 0) {
            int t = warp_tot[lane];
#pragma unroll
            for (int o = 1; o < 32; o <<= 1) {
                int y = __shfl_up_sync(0xFFFFFFFFu, t, o);
                if (lane >= o) t += y;
            }
            warp_tot[lane] = t;
        }
        __syncthreads();
        int wpre = (wid == 0) ? 0 : warp_tot[wid - 1];
        if (i < N_NODES) g_rowptr[i] = carry + wpre + x - v;  // exclusive
        carry += warp_tot[31];
        __syncthreads();
    }
    if (tid == 0) g_rowptr[N_NODES] = carry;
}

__global__ void k_fill(const int* __restrict__ ei) {
    int e = blockIdx.x * blockDim.x + threadIdx.x;
    if (e < N_EDGES) {
        int s = ei[e];
        int d = ei[N_EDGES + e];
        int pos = atomicAdd(&g_cursor[d], 1);
        g_srcidx[g_rowptr[d] + pos] = s;
    }
}

// ---------------- TF32 MMA GEMM: g_h = (act(A) @ W^T) * dinv[row] -----------
// Block tile 128x128x32, 8 warps, warp tile 64x32, mma m16n8k8.
#define BM 128
#define BN 128
#define BK 32

__global__ __launch_bounds__(256)
void k_gemm(const float* __restrict__ Aext, int a_sel,
            const float* __restrict__ W,
            const float* __restrict__ bias, int N, int K) {
    const float* A = Aext ? Aext : buf(a_sel);

    __shared__ float As[BM][BK + 4];   // +4 pad: frag LDS conflict-free
    __shared__ float Ws[BN][BK + 4];

    const int tid  = threadIdx.x;
    const int lane = tid & 31;
    const int wid  = tid >> 5;
    const int wm   = (wid & 1) * 64;   // warp row offset in tile
    const int wn   = (wid >> 1) * 32;  // warp col offset in tile
    const int m0   = blockIdx.x * BM;
    const int n0   = blockIdx.y * BN;
    const int g    = lane >> 2;        // fragment group id (row within 8)
    const int t    = lane & 3;         // thread-in-group (k within 4)
    const int lrow = tid >> 3;         // 0..31 load row
    const int lcol = (tid & 7) * 4;    // load col {0,4,...,28}

    float acc[4][4][4];
#pragma unroll
    for (int i = 0; i < 4; i++)
#pragma unroll
        for (int j = 0; j < 4; j++)
#pragma unroll
            for (int c = 0; c < 4; c++) acc[i][j][c] = 0.0f;

    float4 stA[4], stW[4];

    auto ldg_tile = [&](int kt) {
#pragma unroll
        for (int p = 0; p < 4; p++) {
            int row = p * 32 + lrow;
            int ar = m0 + row;
            if (ar < N)
                stA[p] = *reinterpret_cast<const float4*>(&A[(size_t)ar * K + kt + lcol]);
            else
                stA[p] = make_float4(0.f, 0.f, 0.f, 0.f);
            // W rows n0+row < 256 always (grid.y * BN == D_H)
            stW[p] = *reinterpret_cast<const float4*>(&W[(size_t)(n0 + row) * K + kt + lcol]);
        }
    };

    auto sts_tile = [&](int kt) {
        float bx = 0.f, by = 0.f, bz = 0.f, bw = 0.f;
        if (bias) {
            bx = bias[kt + lcol + 0]; by = bias[kt + lcol + 1];
            bz = bias[kt + lcol + 2]; bw = bias[kt + lcol + 3];
        }
#pragma unroll
        for (int p = 0; p < 4; p++) {
            int row = p * 32 + lrow;
            float4 v = stA[p];
            if (bias) {
                v.x = fmaxf(v.x + bx, 0.f); v.y = fmaxf(v.y + by, 0.f);
                v.z = fmaxf(v.z + bz, 0.f); v.w = fmaxf(v.w + bw, 0.f);
            }
            float4 cv = make_float4(f2tf(v.x), f2tf(v.y), f2tf(v.z), f2tf(v.w));
            *reinterpret_cast<float4*>(&As[row][lcol]) = cv;
            float4 w = stW[p];
            float4 cw = make_float4(f2tf(w.x), f2tf(w.y), f2tf(w.z), f2tf(w.w));
            *reinterpret_cast<float4*>(&Ws[row][lcol]) = cw;
        }
    };

    const int T = K / BK;
    ldg_tile(0);
    sts_tile(0);
    __syncthreads();

    for (int tt = 0; tt < T; tt++) {
        if (tt + 1 < T) ldg_tile((tt + 1) * BK);

#pragma unroll
        for (int ks = 0; ks < 4; ks++) {
            const int kc = ks * 8 + t;
            uint32_t af[4][4], bf[4][2];
#pragma unroll
            for (int i = 0; i < 4; i++) {
                int r = wm + i * 16 + g;
                af[i][0] = __float_as_uint(As[r][kc]);
                af[i][1] = __float_as_uint(As[r + 8][kc]);
                af[i][2] = __float_as_uint(As[r][kc + 4]);
                af[i][3] = __float_as_uint(As[r + 8][kc + 4]);
            }
#pragma unroll
            for (int j = 0; j < 4; j++) {
                int n = wn + j * 8 + g;
                bf[j][0] = __float_as_uint(Ws[n][kc]);
                bf[j][1] = __float_as_uint(Ws[n][kc + 4]);
            }
#pragma unroll
            for (int i = 0; i < 4; i++)
#pragma unroll
                for (int j = 0; j < 4; j++) {
                    asm volatile(
                        "mma.sync.aligned.m16n8k8.row.col.f32.tf32.tf32.f32 "
                        "{%0,%1,%2,%3}, {%4,%5,%6,%7}, {%8,%9}, {%0,%1,%2,%3};"
                        : "+f"(acc[i][j][0]), "+f"(acc[i][j][1]),
                          "+f"(acc[i][j][2]), "+f"(acc[i][j][3])
                        : "r"(af[i][0]), "r"(af[i][1]), "r"(af[i][2]), "r"(af[i][3]),
                          "r"(bf[j][0]), "r"(bf[j][1]));
                }
        }
        __syncthreads();
        if (tt + 1 < T) sts_tile((tt + 1) * BK);
        __syncthreads();
    }

    // epilogue: g_h = acc * dinv[row]
#pragma unroll
    for (int i = 0; i < 4; i++) {
        int r0 = m0 + wm + i * 16 + g;
        int r1 = r0 + 8;
        float dv0 = (r0 < N) ? g_dinv[r0] : 0.f;
        float dv1 = (r1 < N) ? g_dinv[r1] : 0.f;
#pragma unroll
        for (int j = 0; j < 4; j++) {
            int cc = n0 + wn + j * 8 + t * 2;
            if (r0 < N) {
                float2 v = make_float2(acc[i][j][0] * dv0, acc[i][j][1] * dv0);
                *reinterpret_cast<float2*>(&g_h[(size_t)r0 * D_H + cc]) = v;
            }
            if (r1 < N) {
                float2 v = make_float2(acc[i][j][2] * dv1, acc[i][j][3] * dv1);
                *reinterpret_cast<float2*>(&g_h[(size_t)r1 * D_H + cc]) = v;
            }
        }
    }
}

// ------- pull aggregation: out[d] = dinv[d]*(h'[d] + sum h'[src]) -----------
__global__ __launch_bounds__(256)
void k_agg_csr(int out_sel) {
    float* out = buf(out_sel);
    const int d = blockIdx.x;
    const int c = threadIdx.x;
    const int beg = g_rowptr[d];
    const int end = g_rowptr[d + 1];

    __shared__ int s_idx[128];

    float acc = g_h[(size_t)d * D_H + c];   // self-loop term
    for (int b = beg; b < end; b += 128) {
        int m = min(128, end - b);
        if (c < m) s_idx[c] = g_srcidx[b + c];
        __syncthreads();
        int i = 0;
        for (; i + 4 <= m; i += 4) {
            const float* p0 = g_h + (size_t)s_idx[i + 0] * D_H;
            const float* p1 = g_h + (size_t)s_idx[i + 1] * D_H;
            const float* p2 = g_h + (size_t)s_idx[i + 2] * D_H;
            const float* p3 = g_h + (size_t)s_idx[i + 3] * D_H;
            acc += p0[c] + p1[c] + p2[c] + p3[c];
        }
        for (; i < m; i++) acc += g_h[(size_t)s_idx[i] * D_H + c];
        __syncthreads();
    }
    out[(size_t)d * D_H + c] = acc * g_dinv[d];
}

// ---------------- pooling (batch is sorted -> contiguous segments) ----------
__global__ void k_gofs(const int* __restrict__ batch) {
    int n = blockIdx.x * blockDim.x + threadIdx.x;
    if (n >= N_NODES) return;
    int b = batch[n];
    int bp = (n == 0) ? -1 : batch[n - 1];
    for (int g = bp + 1; g <= b; g++) g_gofs[g] = n;
    if (n == N_NODES - 1)
        for (int g = b + 1; g <= N_GRAPHS; g++) g_gofs[g] = N_NODES;
}

__global__ __launch_bounds__(256)
void k_pool(const float* __restrict__ b3) {
    int g = blockIdx.x, c = threadIdx.x;
    int beg = g_gofs[g], end = g_gofs[g + 1];
    float bc = b3[c];
    float acc = 0.0f;
    int n = beg;
    for (; n + 4 <= end; n += 4) {
        float v0 = fmaxf(g_a[(size_t)(n + 0) * D_H + c] + bc, 0.f);
        float v1 = fmaxf(g_a[(size_t)(n + 1) * D_H + c] + bc, 0.f);
        float v2 = fmaxf(g_a[(size_t)(n + 2) * D_H + c] + bc, 0.f);
        float v3 = fmaxf(g_a[(size_t)(n + 3) * D_H + c] + bc, 0.f);
        acc += v0 + v1 + v2 + v3;
    }
    for (; n < end; n++) acc += fmaxf(g_a[(size_t)n * D_H + c] + bc, 0.f);
    float cnt = (float)(end - beg);
    g_pool[g * D_H + c] = acc / fmaxf(cnt, 1.0f);
}

// ---------------- final FC ---------------------------------------------------
__global__ void k_fc(const float* __restrict__ Wfc, const float* __restrict__ bfc,
                     float* __restrict__ out) {
    int g = blockIdx.x;
    int c = threadIdx.x;
    if (c >= N_CLASSES) return;
    const float* p = &g_pool[g * D_H];
    const float* w = &Wfc[c * D_H];
    float s = 0.0f;
#pragma unroll 8
    for (int k = 0; k < D_H; k++) s += p[k] * w[k];
    out[g * N_CLASSES + c] = s + bfc[c];
}

// ---------------- launch -----------------------------------------------------
extern "C" void kernel_launch(void* const* d_in, const int* in_sizes, int n_in,
                              void* d_out, int out_size) {
    const float* x    = (const float*)d_in[0];
    const int*   ei   = (const int*)d_in[1];
    const int*   batch= (const int*)d_in[2];
    const float* W1 = (const float*)d_in[3];
    const float* b1 = (const float*)d_in[4];
    const float* W2 = (const float*)d_in[5];
    const float* b2 = (const float*)d_in[6];
    const float* W3 = (const float*)d_in[7];
    const float* b3 = (const float*)d_in[8];
    const float* Wfc= (const float*)d_in[9];
    const float* bfc= (const float*)d_in[10];
    float* out = (float*)d_out;

    const int A = 1, B = 2;

    // CSR build + dinv
    k_zero_int<<<(N_NODES + 255) / 256, 256>>>();
    k_deg<<<(N_EDGES + 255) / 256, 256>>>(ei);
    k_scan<<<1, 1024>>>();
    k_fill<<<(N_EDGES + 255) / 256, 256>>>(ei);
    k_gofs<<<(N_NODES + 255) / 256, 256>>>(batch);

    dim3 ggrid((N_NODES + BM - 1) / BM, D_H / BN);

    // layer 1
    k_gemm<<<ggrid, 256>>>(x, 0, W1, nullptr, N_NODES, D_IN);
    k_agg_csr<<<N_NODES, 256>>>(A);
    // layer 2
    k_gemm<<<ggrid, 256>>>(nullptr, A, W2, b1, N_NODES, D_H);
    k_agg_csr<<<N_NODES, 256>>>(B);
    // layer 3
    k_gemm<<<ggrid, 256>>>(nullptr, B, W3, b2, N_NODES, D_H);
    k_agg_csr<<<N_NODES, 256>>>(A);

    // pool + fc
    k_pool<<<N_GRAPHS, 256>>>(b3);
    k_fc<<<N_GRAPHS, 64>>>(Wfc, bfc, out);
}

// round 13
// speedup vs baseline: 1.8455x; 1.1176x over previous
#include <cuda_runtime.h>
#include <cuda_bf16.h>
#include <cstdint>

#define N_NODES   30000
#define N_EDGES   480000
#define N_GRAPHS  128
#define D_IN      128
#define D_H       256
#define N_CLASSES 60

// ---------------- scratch (static device globals; no allocation) ------------
__device__ __align__(16) float g_h[(size_t)N_NODES * D_H];  // h' = y*dinv[row]
__device__ __align__(16) float g_a[(size_t)N_NODES * D_H];  // agg out (L1, L3)
__device__ __align__(16) float g_b[(size_t)N_NODES * D_H];  // agg out (L2)
__device__ float g_dinv[N_NODES];
__device__ int   g_degi[N_NODES];
__device__ int   g_cursor[N_NODES];
__device__ int   g_rowptr[N_NODES + 1];
__device__ int   g_srcidx[N_EDGES];
__device__ int   g_gofs[N_GRAPHS + 1];
__device__ float g_pool[N_GRAPHS * D_H];

__device__ __forceinline__ float* buf(int s) {
    return (s == 0) ? g_h : (s == 1) ? g_a : g_b;
}

// round-to-nearest tf32 (unbiased; raw truncation would bias products low)
__device__ __forceinline__ float f2tf(float f) {
    uint32_t u;
    asm("cvt.rna.tf32.f32 %0, %1;" : "=r"(u) : "f"(f));
    return __uint_as_float(u);
}

// ---------------- CSR build --------------------------------------------------
__global__ void k_zero_int() {
    int i = blockIdx.x * blockDim.x + threadIdx.x;
    if (i < N_NODES) { g_degi[i] = 0; g_cursor[i] = 0; }
}

// 4 edges per thread (independent atomic chains; N_EDGES % 4 == 0)
__global__ void k_deg(const int* __restrict__ ei) {
    int t = blockIdx.x * blockDim.x + threadIdx.x;
    if (t * 4 >= N_EDGES) return;
    int4 d4 = *reinterpret_cast<const int4*>(&ei[N_EDGES + t * 4]);
    atomicAdd(&g_degi[d4.x], 1);
    atomicAdd(&g_degi[d4.y], 1);
    atomicAdd(&g_degi[d4.z], 1);
    atomicAdd(&g_degi[d4.w], 1);
}

__global__ void k_dinv() {
    int i = blockIdx.x * blockDim.x + threadIdx.x;
    if (i < N_NODES) g_dinv[i] = rsqrtf((float)(g_degi[i] + 1));  // +1 self loop
}

// single block, 1024 threads: exclusive scan of g_degi -> g_rowptr
__global__ __launch_bounds__(1024)
void k_scan() {
    __shared__ int warp_tot[32];
    int tid = threadIdx.x, lane = tid & 31, wid = tid >> 5;
    int carry = 0;
    for (int base = 0; base < N_NODES; base += 1024) {
        int i = base + tid;
        int v = (i < N_NODES) ? g_degi[i] : 0;
        int x = v;
#pragma unroll
        for (int o = 1; o < 32; o <<= 1) {
            int y = __shfl_up_sync(0xFFFFFFFFu, x, o);
            if (lane >= o) x += y;
        }
        if (lane == 31) warp_tot[wid] = x;
        __syncthreads();
        if (wid == 0) {
            int t = warp_tot[lane];
#pragma unroll
            for (int o = 1; o < 32; o <<= 1) {
                int y = __shfl_up_sync(0xFFFFFFFFu, t, o);
                if (lane >= o) t += y;
            }
            warp_tot[lane] = t;
        }
        __syncthreads();
        int wpre = (wid == 0) ? 0 : warp_tot[wid - 1];
        if (i < N_NODES) g_rowptr[i] = carry + wpre + x - v;  // exclusive
        carry += warp_tot[31];
        __syncthreads();
    }
    if (tid == 0) g_rowptr[N_NODES] = carry;
}

// 4 edges per thread
__global__ void k_fill(const int* __restrict__ ei) {
    int t = blockIdx.x * blockDim.x + threadIdx.x;
    if (t * 4 >= N_EDGES) return;
    int4 s4 = *reinterpret_cast<const int4*>(&ei[t * 4]);
    int4 d4 = *reinterpret_cast<const int4*>(&ei[N_EDGES + t * 4]);
    int p0 = atomicAdd(&g_cursor[d4.x], 1);
    int p1 = atomicAdd(&g_cursor[d4.y], 1);
    int p2 = atomicAdd(&g_cursor[d4.z], 1);
    int p3 = atomicAdd(&g_cursor[d4.w], 1);
    g_srcidx[g_rowptr[d4.x] + p0] = s4.x;
    g_srcidx[g_rowptr[d4.y] + p1] = s4.y;
    g_srcidx[g_rowptr[d4.z] + p2] = s4.z;
    g_srcidx[g_rowptr[d4.w] + p3] = s4.w;
}

// ---------------- TF32 MMA GEMM: g_h = (act(A) @ W^T) * dinv[row] -----------
#define BM 128
#define BN 128
#define BK 32

__global__ __launch_bounds__(256)
void k_gemm(const float* __restrict__ Aext, int a_sel,
            const float* __restrict__ W,
            const float* __restrict__ bias, int N, int K) {
    const float* A = Aext ? Aext : buf(a_sel);

    __shared__ float As[BM][BK + 4];
    __shared__ float Ws[BN][BK + 4];

    const int tid  = threadIdx.x;
    const int lane = tid & 31;
    const int wid  = tid >> 5;
    const int wm   = (wid & 1) * 64;
    const int wn   = (wid >> 1) * 32;
    const int m0   = blockIdx.x * BM;
    const int n0   = blockIdx.y * BN;
    const int g    = lane >> 2;
    const int t    = lane & 3;
    const int lrow = tid >> 3;
    const int lcol = (tid & 7) * 4;

    float acc[4][4][4];
#pragma unroll
    for (int i = 0; i < 4; i++)
#pragma unroll
        for (int j = 0; j < 4; j++)
#pragma unroll
            for (int c = 0; c < 4; c++) acc[i][j][c] = 0.0f;

    float4 stA[4], stW[4];

    auto ldg_tile = [&](int kt) {
#pragma unroll
        for (int p = 0; p < 4; p++) {
            int row = p * 32 + lrow;
            int ar = m0 + row;
            if (ar < N)
                stA[p] = *reinterpret_cast<const float4*>(&A[(size_t)ar * K + kt + lcol]);
            else
                stA[p] = make_float4(0.f, 0.f, 0.f, 0.f);
            stW[p] = *reinterpret_cast<const float4*>(&W[(size_t)(n0 + row) * K + kt + lcol]);
        }
    };

    auto sts_tile = [&](int kt) {
        float bx = 0.f, by = 0.f, bz = 0.f, bw = 0.f;
        if (bias) {
            bx = bias[kt + lcol + 0]; by = bias[kt + lcol + 1];
            bz = bias[kt + lcol + 2]; bw = bias[kt + lcol + 3];
        }
#pragma unroll
        for (int p = 0; p < 4; p++) {
            int row = p * 32 + lrow;
            float4 v = stA[p];
            if (bias) {
                v.x = fmaxf(v.x + bx, 0.f); v.y = fmaxf(v.y + by, 0.f);
                v.z = fmaxf(v.z + bz, 0.f); v.w = fmaxf(v.w + bw, 0.f);
            }
            float4 cv = make_float4(f2tf(v.x), f2tf(v.y), f2tf(v.z), f2tf(v.w));
            *reinterpret_cast<float4*>(&As[row][lcol]) = cv;
            float4 w = stW[p];
            float4 cw = make_float4(f2tf(w.x), f2tf(w.y), f2tf(w.z), f2tf(w.w));
            *reinterpret_cast<float4*>(&Ws[row][lcol]) = cw;
        }
    };

    const int T = K / BK;
    ldg_tile(0);
    sts_tile(0);
    __syncthreads();

    for (int tt = 0; tt < T; tt++) {
        if (tt + 1 < T) ldg_tile((tt + 1) * BK);

#pragma unroll
        for (int ks = 0; ks < 4; ks++) {
            const int kc = ks * 8 + t;
            uint32_t af[4][4], bf[4][2];
#pragma unroll
            for (int i = 0; i < 4; i++) {
                int r = wm + i * 16 + g;
                af[i][0] = __float_as_uint(As[r][kc]);
                af[i][1] = __float_as_uint(As[r + 8][kc]);
                af[i][2] = __float_as_uint(As[r][kc + 4]);
                af[i][3] = __float_as_uint(As[r + 8][kc + 4]);
            }
#pragma unroll
            for (int j = 0; j < 4; j++) {
                int n = wn + j * 8 + g;
                bf[j][0] = __float_as_uint(Ws[n][kc]);
                bf[j][1] = __float_as_uint(Ws[n][kc + 4]);
            }
#pragma unroll
            for (int i = 0; i < 4; i++)
#pragma unroll
                for (int j = 0; j < 4; j++) {
                    asm volatile(
                        "mma.sync.aligned.m16n8k8.row.col.f32.tf32.tf32.f32 "
                        "{%0,%1,%2,%3}, {%4,%5,%6,%7}, {%8,%9}, {%0,%1,%2,%3};"
                        : "+f"(acc[i][j][0]), "+f"(acc[i][j][1]),
                          "+f"(acc[i][j][2]), "+f"(acc[i][j][3])
                        : "r"(af[i][0]), "r"(af[i][1]), "r"(af[i][2]), "r"(af[i][3]),
                          "r"(bf[j][0]), "r"(bf[j][1]));
                }
        }
        __syncthreads();
        if (tt + 1 < T) sts_tile((tt + 1) * BK);
        __syncthreads();
    }

#pragma unroll
    for (int i = 0; i < 4; i++) {
        int r0 = m0 + wm + i * 16 + g;
        int r1 = r0 + 8;
        float dv0 = (r0 < N) ? g_dinv[r0] : 0.f;
        float dv1 = (r1 < N) ? g_dinv[r1] : 0.f;
#pragma unroll
        for (int j = 0; j < 4; j++) {
            int cc = n0 + wn + j * 8 + t * 2;
            if (r0 < N) {
                float2 v = make_float2(acc[i][j][0] * dv0, acc[i][j][1] * dv0);
                *reinterpret_cast<float2*>(&g_h[(size_t)r0 * D_H + cc]) = v;
            }
            if (r1 < N) {
                float2 v = make_float2(acc[i][j][2] * dv1, acc[i][j][3] * dv1);
                *reinterpret_cast<float2*>(&g_h[(size_t)r1 * D_H + cc]) = v;
            }
        }
    }
}

// ------- pull aggregation: out[d] = dinv[d]*(h'[d] + sum h'[src]) -----------
// 256 threads = 4 edge-slots x 64 channel-groups (float4 each)
__global__ __launch_bounds__(256)
void k_agg_csr(int out_sel) {
    float* out = buf(out_sel);
    const int d    = blockIdx.x;
    const int tid  = threadIdx.x;
    const int slot = tid >> 6;          // 0..3
    const int cg   = tid & 63;          // float4 channel group
    const int beg  = g_rowptr[d];
    const int end  = g_rowptr[d + 1];

    __shared__ int    s_idx[128];
    __shared__ float4 s_red[256];

    float4 acc = make_float4(0.f, 0.f, 0.f, 0.f);
    if (slot == 0)
        acc = reinterpret_cast<const float4*>(&g_h[(size_t)d * D_H])[cg];

    for (int b = beg; b < end; b += 128) {
        int m = min(128, end - b);
        if (tid < m) s_idx[tid] = g_srcidx[b + tid];
        __syncthreads();
        for (int i = slot; i < m; i += 4) {
            float4 v = reinterpret_cast<const float4*>(&g_h[(size_t)s_idx[i] * D_H])[cg];
            acc.x += v.x; acc.y += v.y; acc.z += v.z; acc.w += v.w;
        }
        __syncthreads();
    }
    s_red[tid] = acc;
    __syncthreads();
    if (slot == 0) {
        float4 a0 = s_red[cg];
        float4 a1 = s_red[64 + cg];
        float4 a2 = s_red[128 + cg];
        float4 a3 = s_red[192 + cg];
        float dv = g_dinv[d];
        float4 r;
        r.x = (a0.x + a1.x + a2.x + a3.x) * dv;
        r.y = (a0.y + a1.y + a2.y + a3.y) * dv;
        r.z = (a0.z + a1.z + a2.z + a3.z) * dv;
        r.w = (a0.w + a1.w + a2.w + a3.w) * dv;
        reinterpret_cast<float4*>(&out[(size_t)d * D_H])[cg] = r;
    }
}

// ---------------- pooling (batch is sorted -> contiguous segments) ----------
__global__ void k_gofs(const int* __restrict__ batch) {
    int n = blockIdx.x * blockDim.x + threadIdx.x;
    if (n >= N_NODES) return;
    int b = batch[n];
    int bp = (n == 0) ? -1 : batch[n - 1];
    for (int g = bp + 1; g <= b; g++) g_gofs[g] = n;
    if (n == N_NODES - 1)
        for (int g = b + 1; g <= N_GRAPHS; g++) g_gofs[g] = N_NODES;
}

__global__ __launch_bounds__(256)
void k_pool(const float* __restrict__ b3) {
    int g = blockIdx.x, c = threadIdx.x;
    int beg = g_gofs[g], end = g_gofs[g + 1];
    float bc = b3[c];
    float acc = 0.0f;
    int n = beg;
    for (; n + 4 <= end; n += 4) {
        float v0 = fmaxf(g_a[(size_t)(n + 0) * D_H + c] + bc, 0.f);
        float v1 = fmaxf(g_a[(size_t)(n + 1) * D_H + c] + bc, 0.f);
        float v2 = fmaxf(g_a[(size_t)(n + 2) * D_H + c] + bc, 0.f);
        float v3 = fmaxf(g_a[(size_t)(n + 3) * D_H + c] + bc, 0.f);
        acc += v0 + v1 + v2 + v3;
    }
    for (; n < end; n++) acc += fmaxf(g_a[(size_t)n * D_H + c] + bc, 0.f);
    float cnt = (float)(end - beg);
    g_pool[g * D_H + c] = acc / fmaxf(cnt, 1.0f);
}

// ---------------- final FC ---------------------------------------------------
__global__ void k_fc(const float* __restrict__ Wfc, const float* __restrict__ bfc,
                     float* __restrict__ out) {
    int g = blockIdx.x;
    int c = threadIdx.x;
    if (c >= N_CLASSES) return;
    const float* p = &g_pool[g * D_H];
    const float* w = &Wfc[c * D_H];
    float s = 0.0f;
#pragma unroll 8
    for (int k = 0; k < D_H; k++) s += p[k] * w[k];
    out[g * N_CLASSES + c] = s + bfc[c];
}

// ---------------- launch -----------------------------------------------------
extern "C" void kernel_launch(void* const* d_in, const int* in_sizes, int n_in,
                              void* d_out, int out_size) {
    const float* x    = (const float*)d_in[0];
    const int*   ei   = (const int*)d_in[1];
    const int*   batch= (const int*)d_in[2];
    const float* W1 = (const float*)d_in[3];
    const float* b1 = (const float*)d_in[4];
    const float* W2 = (const float*)d_in[5];
    const float* b2 = (const float*)d_in[6];
    const float* W3 = (const float*)d_in[7];
    const float* b3 = (const float*)d_in[8];
    const float* Wfc= (const float*)d_in[9];
    const float* bfc= (const float*)d_in[10];
    float* out = (float*)d_out;

    const int A = 1, B = 2;

    // fork/join plumbing (host-side objects; not in the replayed graph)
    cudaStream_t s1;
    cudaEvent_t e_fork, e_join;
    cudaStreamCreateWithFlags(&s1, cudaStreamNonBlocking);
    cudaEventCreateWithFlags(&e_fork, cudaEventDisableTiming);
    cudaEventCreateWithFlags(&e_join, cudaEventDisableTiming);

    // main stream: degree (needed by dinv AND scan)
    k_zero_int<<<(N_NODES + 255) / 256, 256>>>();
    k_deg<<<(N_EDGES / 4 + 255) / 256, 256>>>(ei);
    cudaEventRecord(e_fork, 0);

    // side stream: CSR scan/fill + pool offsets (overlaps dinv + gemm1)
    cudaStreamWaitEvent(s1, e_fork, 0);
    k_scan<<<1, 1024, 0, s1>>>();
    k_fill<<<(N_EDGES / 4 + 255) / 256, 256, 0, s1>>>(ei);
    k_gofs<<<(N_NODES + 255) / 256, 256, 0, s1>>>(batch);
    cudaEventRecord(e_join, s1);

    // main stream: dinv then layer-1 GEMM
    k_dinv<<<(N_NODES + 255) / 256, 256>>>();
    dim3 ggrid((N_NODES + BM - 1) / BM, D_H / BN);
    k_gemm<<<ggrid, 256>>>(x, 0, W1, nullptr, N_NODES, D_IN);

    // join: aggregation needs CSR
    cudaStreamWaitEvent(0, e_join, 0);
    k_agg_csr<<<N_NODES, 256>>>(A);
    // layer 2
    k_gemm<<<ggrid, 256>>>(nullptr, A, W2, b1, N_NODES, D_H);
    k_agg_csr<<<N_NODES, 256>>>(B);
    // layer 3
    k_gemm<<<ggrid, 256>>>(nullptr, B, W3, b2, N_NODES, D_H);
    k_agg_csr<<<N_NODES, 256>>>(A);

    // pool + fc
    k_pool<<<N_GRAPHS, 256>>>(b3);
    k_fc<<<N_GRAPHS, 64>>>(Wfc, bfc, out);

    cudaEventDestroy(e_fork);
    cudaEventDestroy(e_join);
    cudaStreamDestroy(s1);
}